// round 8
// baseline (speedup 1.0000x reference)
#include <cuda_runtime.h>

// Problem constants: H=64, M=N=128, k=9, w=3
#define PTOT (64 * 128 * 128)
#define KNN  9

// ---- pass1 tile: 16 x 4 x 4, halo 18 x 6 x 6 ----
#define TX 16
#define TY 4
#define TZ 4
#define HX 18
#define HY 6
#define HROWS (HX * HY * 6)     // 648
#define HXY (HX * HY)           // 108

// ---- pass2 tile: 16 x 8 x 4, halo 18 x 10 x 6 ----
#define TY2 8
#define HY2 10
#define H2ROWS (HX * HY2 * 6)   // 1080
#define H2XY (HX * HY2)         // 180

// Scratch: per-voxel 9 selected values (12-float padded row, as 3 float4)
// and 9 window codes (bytes packed in 3 u32 words).
__device__ float4       g_val4[PTOT * 3];    // 50.3 MB
__device__ unsigned int g_code32[PTOT * 3];  // 12.6 MB

// ---------------------------------------------------------------------------
// Pass 1 (unchanged — measured 72.3us): stable top-9 of 27 periodic window
// neighbors by |v - center|.
//   rank(c) = #{j<c: d_j <= d_c} + #{j>c: d_j < d_c}
// One compare per unordered pair, split between FSETP (FMA pipe) and
// ISETP-on-abs-bits (ALU pipe; identical order for d >= 0), with the center
// candidate (13, d=0) algebraically folded into the counter init.
// ---------------------------------------------------------------------------
__global__ __launch_bounds__(256) void pass1_kernel(const float* __restrict__ anat) {
    __shared__ float        s_anat[HROWS];
    __shared__ float4       s_val[256 * 3];
    __shared__ unsigned int s_code[256 * 3];

    int tid = threadIdx.x;
    int lx = tid & 15, ly = (tid >> 4) & 3, lz = tid >> 6;
    int x0 = blockIdx.x * TX, y0 = blockIdx.y * TY, z0 = blockIdx.z * TZ;

    for (int t = tid; t < HROWS; t += 256) {
        int hx = t % HX; int r = t / HX; int hy = r % HY; int hz = r / HY;
        int gx = (x0 + hx + 127) & 127;
        int gy = (y0 + hy + 127) & 127;
        int gz = (z0 + hz + 63) & 63;
        s_anat[t] = __ldg(&anat[(gz << 14) | (gy << 7) | gx]);
    }
    __syncthreads();

    int center = (lz + 1) * HXY + (ly + 1) * HX + (lx + 1);
    float ac = s_anat[center];

    float fd[27];
#pragma unroll
    for (int oz = 0; oz < 3; ++oz)
#pragma unroll
        for (int oy = 0; oy < 3; ++oy)
#pragma unroll
            for (int ox = 0; ox < 3; ++ox) {
                int c = oz * 9 + oy * 3 + ox;
                fd[c] = fabsf(s_anat[center + (oz - 1) * HXY + (oy - 1) * HX + (ox - 1)] - ac);
            }

    // Counter init encodes rank_c += 1 for all c > 13 (pairs with center).
    unsigned ri[7] = { 0u, 0u, 0u, 0x01010000u, 0x01010101u, 0x01010101u, 0x00010101u };
    float    rf[14];
#pragma unroll
    for (int k = 0; k < 14; ++k) rf[k] = 0.0f;

    // Pairs (j<13, c=13): d_j == 0 ?
#pragma unroll
    for (int j = 0; j < 13; ++j) {
        if (__float_as_uint(fd[j]) == 0u)
            ri[3] += (1u << 8);                 // rank_13 byte slot
        else
            ri[j >> 2] += (1u << ((j & 3) * 8));
    }

    // All remaining pairs (both endpoints != 13), diagonal order.
#pragma unroll
    for (int o = 1; o < 27; ++o)
#pragma unroll
        for (int j = 0; j + o < 27; ++j) {
            const int c = j + o;
            if (j == 13 || c == 13) continue;
            if (j & 1) {
                if (__float_as_uint(fd[j]) <= __float_as_uint(fd[c]))
                    ri[c >> 2] += (1u << ((c & 3) * 8));
                else
                    ri[j >> 2] += (1u << ((j & 3) * 8));
            } else {
                if (fd[j] <= fd[c])
                    rf[c >> 1] += ((c & 1) ? 1024.0f : 1.0f);
                else
                    rf[j >> 1] += ((j & 1) ? 1024.0f : 1.0f);
            }
        }

    int fi[14];
#pragma unroll
    for (int k = 0; k < 14; ++k) fi[k] = (int)rf[k];

    float*         svf = (float*)s_val;
    unsigned char* scb = (unsigned char*)s_code;
#pragma unroll
    for (int c = 0; c < 27; ++c) {
        int r = (int)((ri[c >> 2] >> ((c & 3) * 8)) & 255u)
              + ((c & 1) ? (fi[c >> 1] >> 10) : (fi[c >> 1] & 1023));
        if (r < KNN) {
            int oz = c / 9, rem = c - 9 * oz, oy = rem / 3, ox = rem - 3 * oy; // compile-time
            svf[tid * 12 + r] = s_anat[center + (oz - 1) * HXY + (oy - 1) * HX + (ox - 1)];
            scb[tid * 12 + r] = (unsigned char)c;
        }
    }
    __syncthreads();

    // Coalesced copy-out: 16 (lz,ly) lines x 48 float4 per line.
    for (int q = tid; q < 768; q += 256) {
        int line = q / 48, off = q - line * 48;
        int llz = line >> 2, lly = line & 3;
        int vox = ((z0 + llz) << 14) | ((y0 + lly) << 7) | x0;
        g_val4[vox * 3 + off]   = s_val[q];
        g_code32[vox * 3 + off] = s_code[q];
    }
}

// ---------------------------------------------------------------------------
// Pass 2: 512 threads, 16x8x4 tile (halo 1080 rows; halo/interior 2.11).
// Halo loaded FLAT: consecutive thread <-> consecutive float4 (4 sectors per
// warp-instr, each sector touched once), scattered into the scalar stride-9
// smem array (gcd(9,32)=1 keeps divergent row reads near conflict-free).
// Output staged through the same buffer, written back as float4.
// ---------------------------------------------------------------------------
__global__ __launch_bounds__(512) void pass2_kernel(const float* __restrict__ ksig,
                                                    float* __restrict__ out) {
    __shared__ __align__(16) float s9[H2ROWS * 9];   // 38880 B, reused for out staging
    __shared__ int s_tab[27];

    int tid = threadIdx.x;
    int lx = tid & 15, ly = (tid >> 4) & 7, lz = tid >> 7;
    int x0 = blockIdx.x * TX, y0 = blockIdx.y * TY2, z0 = blockIdx.z * TZ;

    if (tid < 27) {
        int oz = tid / 9, rem = tid - 9 * oz, oy = rem / 3, ox = rem - 3 * oy;
        s_tab[tid] = (oz - 1) * H2XY + (oy - 1) * HX + (ox - 1);
    }

    // Flat coalesced halo load: 3240 float4s, scatter to stride-9 scalar rows.
    for (int t = tid; t < H2ROWS * 3; t += 512) {
        int row = t / 3, k = t - row * 3;
        int hx = row % HX; int r = row / HX; int hy = r % HY2; int hz = r / HY2;
        int gx = (x0 + hx + 127) & 127;
        int gy = (y0 + hy + 127) & 127;
        int gz = (z0 + hz + 63) & 63;
        int vox = (gz << 14) | (gy << 7) | gx;
        float4 b = g_val4[vox * 3 + k];
        float* d = &s9[row * 9 + k * 4];
        if (k < 2) { d[0] = b.x; d[1] = b.y; d[2] = b.z; d[3] = b.w; }
        else       { d[0] = b.x; }
    }

    int i = ((z0 + lz) << 14) | ((y0 + ly) << 7) | (x0 + lx);
    unsigned int cw[3];
    cw[0] = g_code32[i * 3];
    cw[1] = g_code32[i * 3 + 1];
    cw[2] = g_code32[i * 3 + 2];
    float ks = __ldg(&ksig[0]);
    __syncthreads();

    int center = (lz + 1) * H2XY + (ly + 1) * HX + (lx + 1);
    float wi[KNN];
#pragma unroll
    for (int t = 0; t < KNN; ++t) wi[t] = s9[center * 9 + t];

    // sigma = std(Wk, ddof=1), two-pass for fp32 stability
    float sum = 0.f;
#pragma unroll
    for (int t = 0; t < KNN; ++t) sum += wi[t];
    float mean = sum * (1.0f / 9.0f);
    float var = 0.f;
#pragma unroll
    for (int t = 0; t < KNN; ++t) { float d = wi[t] - mean; var += d * d; }
    var *= (1.0f / 8.0f);
    float sigma = sqrtf(var);
    bool  zeroSig = (sigma == 0.0f);
    float sig = zeroSig ? 1.0f : sigma;

    // logits = -(||diff|| / sigma / (sqrt(2)*ks))^2 = -s / (2*sigma^2*ks^2)
    float inv = 1.0f / (2.0f * sig * sig * ks * ks);

    float wie[KNN];
#pragma unroll
    for (int t = 0; t < KNN; ++t) wie[t] = wi[t] + 1e-6f;

    float logits[KNN];
#pragma unroll
    for (int j = 0; j < KNN; ++j) {
        int c = (int)((cw[j >> 2] >> ((j & 3) * 8)) & 0xff);
        const float* nr = &s9[(center + s_tab[c]) * 9];
        float s = 0.f;
#pragma unroll
        for (int t = 0; t < KNN; ++t) {
            float df = wie[t] - nr[t];
            s = fmaf(df, df, s);
        }
        logits[j] = zeroSig ? 0.0f : -(s * inv);
    }

    // softmax over the 9 neighbors
    float mx = logits[0];
#pragma unroll
    for (int j = 1; j < KNN; ++j) mx = fmaxf(mx, logits[j]);
    float e[KNN], se = 0.f;
#pragma unroll
    for (int j = 0; j < KNN; ++j) { e[j] = __expf(logits[j] - mx); se += e[j]; }
    float rse = 1.0f / se;

    __syncthreads();                       // all halo reads done; reuse buffer
#pragma unroll
    for (int j = 0; j < KNN; ++j) s9[tid * KNN + j] = e[j] * rse;
    __syncthreads();

    // Coalesced out: 32 lines x 144 floats = 36 float4 per line, 1152 total.
    float4* s_out4 = (float4*)s9;
    for (int q = tid; q < 1152; q += 512) {
        int line = q / 36, off = q - line * 36;
        int llz = line >> 3, lly = line & 7;
        int vox = ((z0 + llz) << 14) | ((y0 + lly) << 7) | x0;
        ((float4*)(out + (size_t)vox * KNN))[off] = s_out4[q];
    }
}

extern "C" void kernel_launch(void* const* d_in, const int* in_sizes, int n_in,
                              void* d_out, int out_size) {
    const float* anat = (const float*)d_in[0];
    const float* ksig = (const float*)d_in[1];
    float* out = (float*)d_out;

    dim3 grid1(128 / TX, 128 / TY, 64 / TZ);    // 8 x 32 x 16 = 4096 blocks
    pass1_kernel<<<grid1, 256>>>(anat);
    dim3 grid2(128 / TX, 128 / TY2, 64 / TZ);   // 8 x 16 x 16 = 2048 blocks
    pass2_kernel<<<grid2, 512>>>(ksig, out);
}